// round 2
// baseline (speedup 1.0000x reference)
#include <cuda_runtime.h>
#include <math.h>

#define B_ROWS 384
#define F_DIM  1024
#define K1_DIM 2048
#define GAMMA_C 1.0e4f

// -------- device scratch (no allocations allowed; kernels reference these directly) --------
__device__ float g_h1[B_ROWS * F_DIM];
__device__ float g_t[B_ROWS * F_DIM];
__device__ int   g_amax[B_ROWS];
__device__ float g_hval[B_ROWS];
__device__ float g_w3t[F_DIM * F_DIM];
__device__ int   g_count[F_DIM];
__device__ float g_list[F_DIM * B_ROWS];

// ---------------- GEMM (NT): C[i,f] = sum_k A[i,k] * W[f,k] (+bias, +extra, relu)
// SRC_H1=0: A comes from params A1 (k<ksplit) / A2 (k>=ksplit), lda=F_DIM.
// SRC_H1=1: A = g_h1.
// DST_T=0: C = g_h1.  DST_T=1: C = g_t.
template<int RELU, int HAS_EXTRA, int SRC_H1, int DST_T>
__global__ void gemm_nt(const float* __restrict__ A1, const float* __restrict__ A2,
                        int ksplit,
                        const float* __restrict__ W,
                        const float* __restrict__ bias,
                        const float* __restrict__ extra,
                        int N, int K)
{
    __shared__ __align__(16) float As[16][68];
    __shared__ __align__(16) float Bs[16][68];

    const int bx = blockIdx.x;   // N tile
    const int by = blockIdx.y;   // M tile
    const int tid = threadIdx.x; // 256
    const int tx = tid & 15;
    const int ty = tid >> 4;

    const int lrow = tid >> 2;          // 0..63
    const int lk4  = (tid & 3) << 2;    // 0,4,8,12

    float acc[4][4];
#pragma unroll
    for (int i = 0; i < 4; i++)
#pragma unroll
        for (int j = 0; j < 4; j++) acc[i][j] = 0.0f;

    const int rowA = by * 64 + lrow;
    const int rowB = bx * 64 + lrow;

    for (int k0 = 0; k0 < K; k0 += 16) {
        const float* Ab;
        int kc;
        if (SRC_H1) { Ab = g_h1; kc = k0; }
        else if (k0 < ksplit) { Ab = A1; kc = k0; }
        else { Ab = A2; kc = k0 - ksplit; }

        float4 av = *reinterpret_cast<const float4*>(Ab + (size_t)rowA * F_DIM + kc + lk4);
        float4 bv = *reinterpret_cast<const float4*>(W  + (size_t)rowB * K     + k0 + lk4);

        As[lk4 + 0][lrow] = av.x;
        As[lk4 + 1][lrow] = av.y;
        As[lk4 + 2][lrow] = av.z;
        As[lk4 + 3][lrow] = av.w;
        Bs[lk4 + 0][lrow] = bv.x;
        Bs[lk4 + 1][lrow] = bv.y;
        Bs[lk4 + 2][lrow] = bv.z;
        Bs[lk4 + 3][lrow] = bv.w;
        __syncthreads();

#pragma unroll
        for (int k = 0; k < 16; k++) {
            float4 a = *reinterpret_cast<const float4*>(&As[k][ty * 4]);
            float4 b = *reinterpret_cast<const float4*>(&Bs[k][tx * 4]);
            acc[0][0] += a.x * b.x; acc[0][1] += a.x * b.y; acc[0][2] += a.x * b.z; acc[0][3] += a.x * b.w;
            acc[1][0] += a.y * b.x; acc[1][1] += a.y * b.y; acc[1][2] += a.y * b.z; acc[1][3] += a.y * b.w;
            acc[2][0] += a.z * b.x; acc[2][1] += a.z * b.y; acc[2][2] += a.z * b.z; acc[2][3] += a.z * b.w;
            acc[3][0] += a.w * b.x; acc[3][1] += a.w * b.y; acc[3][2] += a.w * b.z; acc[3][3] += a.w * b.w;
        }
        __syncthreads();
    }

    float* C = DST_T ? g_t : g_h1;
    const int row0 = by * 64 + ty * 4;
    const int col0 = bx * 64 + tx * 4;
#pragma unroll
    for (int m = 0; m < 4; m++) {
#pragma unroll
        for (int n = 0; n < 4; n++) {
            float v = acc[m][n] + bias[col0 + n];
            if (HAS_EXTRA) v += extra[(size_t)(row0 + m) * N + col0 + n];
            if (RELU) v = fmaxf(v, 0.0f);
            C[(size_t)(row0 + m) * N + col0 + n] = v;
        }
    }
}

// ---------------- per-row argmax + softmax max-prob -> hval
__global__ void row_softmax_argmax()
{
    const int r = blockIdx.x;
    const float* tr = g_t + (size_t)r * F_DIM;
    const int tid = threadIdx.x; // 256

    __shared__ float sv[256];
    __shared__ int   si[256];

    float bv = -3.402823466e38f;
    int bi = 0;
    for (int f = tid; f < F_DIM; f += 256) {
        float v = tr[f];
        if (v > bv) { bv = v; bi = f; }   // ascending f -> first occurrence kept
    }
    sv[tid] = bv; si[tid] = bi;
    __syncthreads();
    for (int s = 128; s > 0; s >>= 1) {
        if (tid < s) {
            float ov = sv[tid + s]; int oi = si[tid + s];
            if (ov > sv[tid] || (ov == sv[tid] && oi < si[tid])) { sv[tid] = ov; si[tid] = oi; }
        }
        __syncthreads();
    }
    const float mx = sv[0];
    const int   ix = si[0];
    __syncthreads();

    float lsum = 0.0f;
    for (int f = tid; f < F_DIM; f += 256) lsum += expf(tr[f] - mx);
    sv[tid] = lsum;
    __syncthreads();
    for (int s = 128; s > 0; s >>= 1) {
        if (tid < s) sv[tid] += sv[tid + s];
        __syncthreads();
    }
    if (tid == 0) {
        g_amax[r] = ix;
        float smax = 1.0f / sv[0];                       // y_soft at argmax
        // replicate h2 = (1 - y_soft) + y_soft exactly as fp32 does
        float h = __fadd_rn(__fadd_rn(1.0f, -smax), smax);
        g_hval[r] = h;
    }
}

// ---------------- transpose W3 -> g_w3t (for coalesced reads in final kernel)
__global__ void transpose_k(const float* __restrict__ in)
{
    __shared__ float tile[32][33];
    int x = blockIdx.x * 32 + threadIdx.x;
    int y = blockIdx.y * 32 + threadIdx.y;
#pragma unroll
    for (int j = 0; j < 32; j += 8)
        tile[threadIdx.y + j][threadIdx.x] = in[(size_t)(y + j) * F_DIM + x];
    __syncthreads();
    x = blockIdx.y * 32 + threadIdx.x;
    y = blockIdx.x * 32 + threadIdx.y;
#pragma unroll
    for (int j = 0; j < 32; j += 8)
        g_w3t[(size_t)(y + j) * F_DIM + x] = tile[threadIdx.x][threadIdx.y + j];
}

// ---------------- invert argmax: per-feature count + deterministic hval list
__global__ void build_lists()
{
    __shared__ int sa[B_ROWS];
    const int tid = threadIdx.x; // 1024
    if (tid < B_ROWS) sa[tid] = g_amax[tid];
    __syncthreads();
    if (tid < F_DIM) {
        int c = 0;
        for (int j = 0; j < B_ROWS; j++) c += (sa[j] == tid) ? 1 : 0;
        g_count[tid] = c;
    }
    if (tid < B_ROWS) {
        int a = sa[tid];
        int slot = 0;
        for (int j = 0; j < tid; j++) slot += (sa[j] == a) ? 1 : 0;
        g_list[(size_t)a * B_ROWS + slot] = g_hval[tid];
    }
}

// ---------------- final: pr[i,f] = aB*(B*q0 + corrections) + beta
__global__ void final_kernel(const float* __restrict__ b3,
                             float* __restrict__ out, float aB, float beta)
{
    const int i = blockIdx.x;
    const int tid = threadIdx.x; // 256
    const float hvi = g_hval[i];
    const int ai = g_amax[i];
    const float* wrow = g_w3t + (size_t)ai * F_DIM;

    for (int f = tid; f < F_DIM; f += 256) {
        float z = __fmul_rn(hvi, wrow[f]) + b3[f];   // z3[i,f]
        float q0 = 1.0f / (1.0f + GAMMA_C * z * z);
        float acc = 384.0f * q0;
        int c = g_count[f];
        for (int s = 0; s < c; s++) {
            float d = z - g_list[(size_t)f * B_ROWS + s];
            acc += 1.0f / (1.0f + GAMMA_C * d * d) - q0;
        }
        out[(size_t)i * F_DIM + f] = aB * acc + beta;
    }
}

extern "C" void kernel_launch(void* const* d_in, const int* in_sizes, int n_in,
                              void* d_out, int out_size)
{
    const float* x      = (const float*)d_in[0];
    const float* m      = (const float*)d_in[1];
    const float* gumbel = (const float*)d_in[2];
    const float* W1     = (const float*)d_in[3];
    const float* b1     = (const float*)d_in[4];
    const float* W2     = (const float*)d_in[5];
    const float* b2     = (const float*)d_in[6];
    const float* W3     = (const float*)d_in[7];
    const float* b3     = (const float*)d_in[8];
    float* out = (float*)d_out;

    // alpha/beta exactly as _prob does (float64 then cast to float32)
    double s = 0.0;
    for (int k = 1; k <= B_ROWS - 1; k++) s += 1.0 / (double)k;
    double theta = 1.0 / s;
    float alpha = (float)((double)B_ROWS / ((double)B_ROWS + theta));
    float beta  = (float)(0.5 * theta / ((double)B_ROWS + theta));
    float aB    = alpha / (float)B_ROWS;

    // GEMM1: h1 = relu([x|m] @ W1^T + b1)   M=384, N=1024, K=2048
    gemm_nt<1, 0, 0, 0><<<dim3(F_DIM / 64, B_ROWS / 64), 256>>>(
        x, m, F_DIM, W1, b1, (const float*)nullptr, F_DIM, K1_DIM);

    // transpose W3 (independent of GEMMs, runs concurrently where possible)
    transpose_k<<<dim3(F_DIM / 32, F_DIM / 32), dim3(32, 8)>>>(W3);

    // GEMM2: t = h1 @ W2^T + b2 + gumbel    M=384, N=1024, K=1024
    gemm_nt<0, 1, 1, 1><<<dim3(F_DIM / 64, B_ROWS / 64), 256>>>(
        (const float*)nullptr, (const float*)nullptr, 0, W2, b2, gumbel, F_DIM, F_DIM);

    row_softmax_argmax<<<B_ROWS, 256>>>();
    build_lists<<<1, 1024>>>();
    final_kernel<<<B_ROWS, 256>>>(b3, out, aB, beta);
}

// round 4
// speedup vs baseline: 1.2231x; 1.2231x over previous
#include <cuda_runtime.h>
#include <math.h>

#define B_ROWS 384
#define F_DIM  1024
#define GAMMA_C 1.0e4f
#define S_BF   (B_ROWS * F_DIM)

typedef unsigned long long ull;

// -------- device scratch (no allocations; kernels reference directly) --------
__device__ float g_h1[S_BF];
__device__ float g_p1[3 * S_BF];
__device__ float g_p2[3 * S_BF];
__device__ int   g_amax[B_ROWS];
__device__ float g_hval[B_ROWS];
__device__ int   g_count[F_DIM];
__device__ float g_list[F_DIM * B_ROWS];

__device__ __forceinline__ ull pack_dup(float v) {
    ull p;
    asm("mov.b64 %0, {%1, %1};" : "=l"(p) : "f"(v));
    return p;
}
__device__ __forceinline__ void ffma2(ull& acc, ull a, ull b) {
    asm("fma.rn.f32x2 %0, %1, %2, %0;" : "+l"(acc) : "l"(a), "l"(b));
}
__device__ __forceinline__ float2 unpack2(ull v) {
    float2 r;
    asm("mov.b64 {%0, %1}, %2;" : "=f"(r.x), "=f"(r.y) : "l"(v));
    return r;
}

// ---------------- FFMA2 GEMM (NT), tile 64x64, 128 threads, split-K=3 over blockIdx.z.
// C_partial[z][i,f] = sum_{k in z-range} A[i,k] * W[f,k]
// WHICH=1: A = concat(x|m) at k=1024, K=2048, dest g_p1.
// WHICH=2: A = g_h1, K=1024, dest g_p2.
template<int WHICH>
__global__ void __launch_bounds__(128) gemm_ffma2(const float* __restrict__ A1,
                                                  const float* __restrict__ A2,
                                                  const float* __restrict__ W, int K)
{
    __shared__ __align__(16) float Asd[32][136];  // [k][2*m] duplicated pairs {v,v}
    __shared__ __align__(16) float Bs[32][72];    // [k][n]

    const int bx = blockIdx.x;          // N tile (16)
    const int by = blockIdx.y;          // M tile (6)
    const int z  = blockIdx.z;          // K split (3)
    const int tid = threadIdx.x;        // 128

    int kb, ke;
    if (WHICH == 1) { kb = z * 672;  ke = (z == 2) ? 2048 : kb + 672; }
    else            { kb = z * 352;  ke = (z == 2) ? 1024 : kb + 352; }

    const int tn = tid & 7;             // 0..7  -> n0 = tn*8
    const int tm = tid >> 3;            // 0..15 -> m0 = tm*4
    const int n0 = tn * 8;
    const int m2 = tm * 8;              // 2*m0 in Asd cols

    const int lm = tid >> 1;            // 0..63 (fill row)
    const int kh = (tid & 1) * 16;      // fill k-half

    ull acc[4][4];
#pragma unroll
    for (int i = 0; i < 4; i++)
#pragma unroll
        for (int j = 0; j < 4; j++) acc[i][j] = 0ull;

    const size_t rowAoff = (size_t)(by * 64 + lm) * F_DIM;
    const size_t rowWoff = (size_t)(bx * 64 + lm) * K;

    for (int k0 = kb; k0 < ke; k0 += 32) {
        const float* Ab; int kc;
        if (WHICH == 1) {
            if (k0 < 1024) { Ab = A1; kc = k0; } else { Ab = A2; kc = k0 - 1024; }
        } else { Ab = g_h1; kc = k0; }

        const float* ap = Ab + rowAoff + kc + kh;
        const float* wp = W + rowWoff + k0 + kh;
#pragma unroll
        for (int q = 0; q < 4; q++) {
            float4 a = *reinterpret_cast<const float4*>(ap + q * 4);
            float4 b = *reinterpret_cast<const float4*>(wp + q * 4);
            const int kk = kh + q * 4;
            *reinterpret_cast<ull*>(&Asd[kk + 0][2 * lm]) = pack_dup(a.x);
            *reinterpret_cast<ull*>(&Asd[kk + 1][2 * lm]) = pack_dup(a.y);
            *reinterpret_cast<ull*>(&Asd[kk + 2][2 * lm]) = pack_dup(a.z);
            *reinterpret_cast<ull*>(&Asd[kk + 3][2 * lm]) = pack_dup(a.w);
            Bs[kk + 0][lm] = b.x;
            Bs[kk + 1][lm] = b.y;
            Bs[kk + 2][lm] = b.z;
            Bs[kk + 3][lm] = b.w;
        }
        __syncthreads();

#pragma unroll
        for (int kk = 0; kk < 32; kk++) {
            ulonglong2 aA = *reinterpret_cast<const ulonglong2*>(&Asd[kk][m2]);
            ulonglong2 aB = *reinterpret_cast<const ulonglong2*>(&Asd[kk][m2 + 4]);
            ulonglong2 bA = *reinterpret_cast<const ulonglong2*>(&Bs[kk][n0]);
            ulonglong2 bB = *reinterpret_cast<const ulonglong2*>(&Bs[kk][n0 + 4]);
            ull am0 = aA.x, am1 = aA.y, am2_ = aB.x, am3 = aB.y;
            ull bn0 = bA.x, bn1 = bA.y, bn2 = bB.x, bn3 = bB.y;
            ffma2(acc[0][0], am0, bn0); ffma2(acc[0][1], am0, bn1);
            ffma2(acc[0][2], am0, bn2); ffma2(acc[0][3], am0, bn3);
            ffma2(acc[1][0], am1, bn0); ffma2(acc[1][1], am1, bn1);
            ffma2(acc[1][2], am1, bn2); ffma2(acc[1][3], am1, bn3);
            ffma2(acc[2][0], am2_, bn0); ffma2(acc[2][1], am2_, bn1);
            ffma2(acc[2][2], am2_, bn2); ffma2(acc[2][3], am2_, bn3);
            ffma2(acc[3][0], am3, bn0); ffma2(acc[3][1], am3, bn1);
            ffma2(acc[3][2], am3, bn2); ffma2(acc[3][3], am3, bn3);
        }
        __syncthreads();
    }

    float* P = (WHICH == 1 ? g_p1 : g_p2) + (size_t)z * S_BF;
    const int row0 = by * 64 + tm * 4;
    const int col0 = bx * 64 + n0;
#pragma unroll
    for (int mm = 0; mm < 4; mm++) {
        float2 p0 = unpack2(acc[mm][0]);
        float2 p1 = unpack2(acc[mm][1]);
        float2 p2 = unpack2(acc[mm][2]);
        float2 p3 = unpack2(acc[mm][3]);
        float4 c0 = make_float4(p0.x, p0.y, p1.x, p1.y);
        float4 c1 = make_float4(p2.x, p2.y, p3.x, p3.y);
        float* dst = P + (size_t)(row0 + mm) * F_DIM + col0;
        *reinterpret_cast<float4*>(dst) = c0;
        *reinterpret_cast<float4*>(dst + 4) = c1;
    }
}

// ---------------- combine GEMM1 partials: h1 = relu(p0+p1+p2 + b1[col])
__global__ void combine1(const float* __restrict__ b1)
{
    const int i4 = blockIdx.x * 256 + threadIdx.x;   // float4 index, 98304 total
    const float4 a = reinterpret_cast<const float4*>(g_p1)[i4];
    const float4 b = reinterpret_cast<const float4*>(g_p1 + S_BF)[i4];
    const float4 c = reinterpret_cast<const float4*>(g_p1 + 2 * S_BF)[i4];
    const float4 bb = reinterpret_cast<const float4*>(b1)[i4 & 255];
    float4 r;
    r.x = fmaxf(a.x + b.x + c.x + bb.x, 0.0f);
    r.y = fmaxf(a.y + b.y + c.y + bb.y, 0.0f);
    r.z = fmaxf(a.z + b.z + c.z + bb.z, 0.0f);
    r.w = fmaxf(a.w + b.w + c.w + bb.w, 0.0f);
    reinterpret_cast<float4*>(g_h1)[i4] = r;
}

// ---------------- combine GEMM2 partials + bias + gumbel, then argmax + softmax-at-max
__global__ void row_softmax_argmax(const float* __restrict__ b2,
                                   const float* __restrict__ gumbel)
{
    const int r = blockIdx.x;
    const int tid = threadIdx.x;  // 256
    __shared__ float t[F_DIM];
    __shared__ float sv[256];
    __shared__ int   si[256];

    const size_t base = (size_t)r * F_DIM;
    for (int f = tid; f < F_DIM; f += 256) {
        float v = g_p2[base + f] + g_p2[S_BF + base + f] + g_p2[2 * S_BF + base + f]
                + b2[f] + gumbel[base + f];
        t[f] = v;
    }
    __syncthreads();

    float bv = -3.402823466e38f;
    int bi = 0;
    for (int f = tid; f < F_DIM; f += 256) {
        float v = t[f];
        if (v > bv) { bv = v; bi = f; }   // ascending f -> first occurrence
    }
    sv[tid] = bv; si[tid] = bi;
    __syncthreads();
    for (int s = 128; s > 0; s >>= 1) {
        if (tid < s) {
            float ov = sv[tid + s]; int oi = si[tid + s];
            if (ov > sv[tid] || (ov == sv[tid] && oi < si[tid])) { sv[tid] = ov; si[tid] = oi; }
        }
        __syncthreads();
    }
    const float mx = sv[0];
    const int   ix = si[0];
    __syncthreads();

    float lsum = 0.0f;
    for (int f = tid; f < F_DIM; f += 256) lsum += expf(t[f] - mx);
    sv[tid] = lsum;
    __syncthreads();
    for (int s = 128; s > 0; s >>= 1) {
        if (tid < s) sv[tid] += sv[tid + s];
        __syncthreads();
    }
    if (tid == 0) {
        g_amax[r] = ix;
        float smax = 1.0f / sv[0];                        // y_soft at argmax
        float h = __fadd_rn(__fadd_rn(1.0f, -smax), smax); // (1 - s) + s in fp32
        g_hval[r] = h;
    }
}

// ---------------- invert argmax: per-feature count + deterministic hval list
__global__ void build_lists()
{
    __shared__ int sa[B_ROWS];
    const int tid = threadIdx.x; // 1024
    if (tid < B_ROWS) sa[tid] = g_amax[tid];
    __syncthreads();
    if (tid < F_DIM) {
        int c = 0;
        for (int j = 0; j < B_ROWS; j++) c += (sa[j] == tid) ? 1 : 0;
        g_count[tid] = c;
    }
    if (tid < B_ROWS) {
        int a = sa[tid];
        int slot = 0;
        for (int j = 0; j < tid; j++) slot += (sa[j] == a) ? 1 : 0;
        g_list[(size_t)a * B_ROWS + slot] = g_hval[tid];
    }
}

// ---------------- final: pr[i,f] = aB*(B*q0 + corrections) + beta
__global__ void final_kernel(const float* __restrict__ W3, const float* __restrict__ b3,
                             float* __restrict__ out, float aB, float beta)
{
    const int i = blockIdx.x;
    const int tid = threadIdx.x; // 256
    const float hvi = g_hval[i];
    const int ai = g_amax[i];

    for (int f = tid; f < F_DIM; f += 256) {
        float z = __fmul_rn(hvi, W3[(size_t)f * F_DIM + ai]) + b3[f];  // z3[i,f]
        float q0 = 1.0f / (1.0f + GAMMA_C * z * z);
        float acc = 384.0f * q0;
        int c = g_count[f];
        for (int s = 0; s < c; s++) {
            float d = z - g_list[(size_t)f * B_ROWS + s];
            acc += 1.0f / (1.0f + GAMMA_C * d * d) - q0;
        }
        out[(size_t)i * F_DIM + f] = aB * acc + beta;
    }
}

extern "C" void kernel_launch(void* const* d_in, const int* in_sizes, int n_in,
                              void* d_out, int out_size)
{
    const float* x      = (const float*)d_in[0];
    const float* m      = (const float*)d_in[1];
    const float* gumbel = (const float*)d_in[2];
    const float* W1     = (const float*)d_in[3];
    const float* b1     = (const float*)d_in[4];
    const float* W2     = (const float*)d_in[5];
    const float* b2     = (const float*)d_in[6];
    const float* W3     = (const float*)d_in[7];
    const float* b3     = (const float*)d_in[8];
    float* out = (float*)d_out;

    // alpha/beta exactly as _prob (float64 then cast)
    double s = 0.0;
    for (int k = 1; k <= B_ROWS - 1; k++) s += 1.0 / (double)k;
    double theta = 1.0 / s;
    float alpha = (float)((double)B_ROWS / ((double)B_ROWS + theta));
    float beta  = (float)(0.5 * theta / ((double)B_ROWS + theta));
    float aB    = alpha / (float)B_ROWS;

    // GEMM1 (split-K=3): partials of [x|m] @ W1^T   M=384, N=1024, K=2048
    gemm_ffma2<1><<<dim3(16, 6, 3), 128>>>(x, m, W1, 2048);
    combine1<<<384, 256>>>(b1);

    // GEMM2 (split-K=3): partials of h1 @ W2^T      M=384, N=1024, K=1024
    gemm_ffma2<2><<<dim3(16, 6, 3), 128>>>(nullptr, nullptr, W2, 1024);

    row_softmax_argmax<<<B_ROWS, 256>>>(b2, gumbel);
    build_lists<<<1, 1024>>>();
    final_kernel<<<B_ROWS, 256>>>(W3, b3, out, aB, beta);
}

// round 6
// speedup vs baseline: 2.5340x; 2.0718x over previous
#include <cuda_runtime.h>
#include <math.h>
#include <stdint.h>

#define B_ROWS 384
#define F_DIM  1024
#define GAMMA_C 1.0e4f
#define S_BF   (B_ROWS * F_DIM)
#define KSPLIT 6
#define TSTR   20      // smem tile row stride in floats (16 data + 4 pad)

// -------- device scratch (no allocations) --------
__device__ float g_h1[S_BF];
__device__ float g_p1[KSPLIT * S_BF];
__device__ float g_p2[KSPLIT * S_BF];
__device__ int   g_amax[B_ROWS];
__device__ float g_hval[B_ROWS];
__device__ int   g_count[F_DIM];
__device__ float g_list[F_DIM * B_ROWS];

// ---------------- helpers ----------------
__device__ __forceinline__ uint32_t smem_u32(const void* p) {
    uint32_t a;
    asm("{ .reg .u64 t; cvta.to.shared.u64 t, %1; cvt.u32.u64 %0, t; }" : "=r"(a) : "l"(p));
    return a;
}
__device__ __forceinline__ void cvt_hilo(float x, float& h, float& l) {
    uint32_t hb, lb;
    asm("cvt.rna.tf32.f32 %0, %1;" : "=r"(hb) : "f"(x));
    h = __uint_as_float(hb);
    float r = x - h;
    asm("cvt.rna.tf32.f32 %0, %1;" : "=r"(lb) : "f"(r));
    l = __uint_as_float(lb);
}
__device__ __forceinline__ void ldsm4(uint32_t* r, uint32_t addr) {
    asm volatile("ldmatrix.sync.aligned.m8n8.x4.shared.b16 {%0,%1,%2,%3}, [%4];"
        : "=r"(r[0]), "=r"(r[1]), "=r"(r[2]), "=r"(r[3]) : "r"(addr));
}
__device__ __forceinline__ void mma_tf32(float* d, const uint32_t* a, uint32_t b0, uint32_t b1) {
    asm volatile("mma.sync.aligned.m16n8k8.row.col.f32.tf32.tf32.f32 "
        "{%0,%1,%2,%3}, {%4,%5,%6,%7}, {%8,%9}, {%0,%1,%2,%3};"
        : "+f"(d[0]), "+f"(d[1]), "+f"(d[2]), "+f"(d[3])
        : "r"(a[0]), "r"(a[1]), "r"(a[2]), "r"(a[3]), "r"(b0), "r"(b1));
}

// ---------------- 3xTF32 mma.sync GEMM (NT). CTA tile 128x128, 256 threads.
// C_partial[z][i,f] = sum_{k in z range} A[i,k] * W[f,k]
// WHICH=1: A = concat(x|m) (split at k=1024), K=2048, dest g_p1.
// WHICH=2: A = g_h1, K=1024, dest g_p2.
template<int WHICH>
__global__ void __launch_bounds__(256) gemm_mma(const float* __restrict__ A1,
                                                const float* __restrict__ A2,
                                                const float* __restrict__ W, int K)
{
    __shared__ __align__(16) float sAh[128 * TSTR];
    __shared__ __align__(16) float sAl[128 * TSTR];
    __shared__ __align__(16) float sBh[128 * TSTR];
    __shared__ __align__(16) float sBl[128 * TSTR];

    const int tid  = threadIdx.x;
    const int lane = tid & 31;
    const int wid  = tid >> 5;
    const int wm   = wid >> 2;      // 0..1  -> m offset wm*64
    const int wn   = wid & 3;       // 0..3  -> n offset wn*32
    const int bx = blockIdx.x;      // N tile (8)
    const int by = blockIdx.y;      // M tile (3)
    const int z  = blockIdx.z;      // K split (6)

    const int chunks_total = K / 16;
    const int cbase = chunks_total / KSPLIT;
    const int crem  = chunks_total % KSPLIT;
    const int nch   = cbase + (z < crem ? 1 : 0);
    const int cstart = z * cbase + (z < crem ? z : crem);

    // ldmatrix per-thread source addresses (byte offsets into tiles)
    const int sub = lane >> 3, rr = lane & 7;
    const uint32_t aAh = smem_u32(sAh), aAl = smem_u32(sAl);
    const uint32_t aBh = smem_u32(sBh), aBl = smem_u32(sBl);
    const uint32_t a_off = ((uint32_t)((wm * 64 + (sub & 1) * 8 + rr) * TSTR + (sub >> 1) * 4)) * 4u;
    const uint32_t b_off = ((uint32_t)((wn * 32 + (sub >> 1) * 8 + rr) * TSTR + (sub & 1) * 4)) * 4u;

    float acc[4][4][4];
#pragma unroll
    for (int i = 0; i < 4; i++)
#pragma unroll
        for (int j = 0; j < 4; j++)
#pragma unroll
            for (int q = 0; q < 4; q++) acc[i][j][q] = 0.0f;

    // prefetch indices: f4 = it*256 + tid; row = f4>>2 (128 rows x 4 float4), c4 = f4&3
    float4 pa[2], pb[2];
    {
        const int kb = cstart * 16;
#pragma unroll
        for (int it = 0; it < 2; it++) {
            const int f4 = it * 256 + tid;
            const int row = f4 >> 2, c4 = f4 & 3;
            const float* Ab; int kc;
            if (WHICH == 1) { if (kb < 1024) { Ab = A1; kc = kb; } else { Ab = A2; kc = kb - 1024; } }
            else            { Ab = g_h1; kc = kb; }
            pa[it] = *reinterpret_cast<const float4*>(Ab + (size_t)(by * 128 + row) * F_DIM + kc + c4 * 4);
            pb[it] = *reinterpret_cast<const float4*>(W + (size_t)(bx * 128 + row) * K + kb + c4 * 4);
        }
    }

    for (int c = 0; c < nch; c++) {
        // ---- convert current chunk to smem (hi/lo)
#pragma unroll
        for (int it = 0; it < 2; it++) {
            const int f4 = it * 256 + tid;
            const int row = f4 >> 2, c4 = f4 & 3;
            const int off = row * TSTR + c4 * 4;
            float4 h, l;
            cvt_hilo(pa[it].x, h.x, l.x); cvt_hilo(pa[it].y, h.y, l.y);
            cvt_hilo(pa[it].z, h.z, l.z); cvt_hilo(pa[it].w, h.w, l.w);
            *reinterpret_cast<float4*>(&sAh[off]) = h;
            *reinterpret_cast<float4*>(&sAl[off]) = l;
            cvt_hilo(pb[it].x, h.x, l.x); cvt_hilo(pb[it].y, h.y, l.y);
            cvt_hilo(pb[it].z, h.z, l.z); cvt_hilo(pb[it].w, h.w, l.w);
            *reinterpret_cast<float4*>(&sBh[off]) = h;
            *reinterpret_cast<float4*>(&sBl[off]) = l;
        }
        __syncthreads();

        // ---- prefetch next chunk (overlaps mma)
        if (c + 1 < nch) {
            const int kb = (cstart + c + 1) * 16;
#pragma unroll
            for (int it = 0; it < 2; it++) {
                const int f4 = it * 256 + tid;
                const int row = f4 >> 2, c4 = f4 & 3;
                const float* Ab; int kc;
                if (WHICH == 1) { if (kb < 1024) { Ab = A1; kc = kb; } else { Ab = A2; kc = kb - 1024; } }
                else            { Ab = g_h1; kc = kb; }
                pa[it] = *reinterpret_cast<const float4*>(Ab + (size_t)(by * 128 + row) * F_DIM + kc + c4 * 4);
                pb[it] = *reinterpret_cast<const float4*>(W + (size_t)(bx * 128 + row) * K + kb + c4 * 4);
            }
        }

        // ---- mma over the chunk: 2 k-steps of 8
#pragma unroll
        for (int ks = 0; ks < 2; ks++) {
            uint32_t Ah[4][4], Al[4][4], Bh[2][4], Bl[2][4];
            const uint32_t kso = (uint32_t)(ks * 32);
#pragma unroll
            for (int mt = 0; mt < 4; mt++) {
                ldsm4(Ah[mt], aAh + a_off + mt * (16 * TSTR * 4) + kso);
                ldsm4(Al[mt], aAl + a_off + mt * (16 * TSTR * 4) + kso);
            }
#pragma unroll
            for (int p = 0; p < 2; p++) {
                ldsm4(Bh[p], aBh + b_off + p * (16 * TSTR * 4) + kso);
                ldsm4(Bl[p], aBl + b_off + p * (16 * TSTR * 4) + kso);
            }
#pragma unroll
            for (int mt = 0; mt < 4; mt++) {
#pragma unroll
                for (int nt = 0; nt < 4; nt++) {
                    const uint32_t* bh = &Bh[nt >> 1][(nt & 1) * 2];
                    const uint32_t* bl = &Bl[nt >> 1][(nt & 1) * 2];
                    mma_tf32(acc[mt][nt], Ah[mt], bh[0], bh[1]);   // hi*hi
                    mma_tf32(acc[mt][nt], Ah[mt], bl[0], bl[1]);   // hi*lo
                    mma_tf32(acc[mt][nt], Al[mt], bh[0], bh[1]);   // lo*hi
                }
            }
        }
        __syncthreads();
    }

    // ---- epilogue: write partials
    float* P = (WHICH == 1 ? g_p1 : g_p2) + (size_t)z * S_BF;
    const int g = lane >> 2, tig = lane & 3;
#pragma unroll
    for (int mt = 0; mt < 4; mt++) {
        const int row0 = by * 128 + wm * 64 + mt * 16 + g;
#pragma unroll
        for (int nt = 0; nt < 4; nt++) {
            const int col0 = bx * 128 + wn * 32 + nt * 8 + tig * 2;
            *reinterpret_cast<float2*>(P + (size_t)row0 * F_DIM + col0) =
                make_float2(acc[mt][nt][0], acc[mt][nt][1]);
            *reinterpret_cast<float2*>(P + (size_t)(row0 + 8) * F_DIM + col0) =
                make_float2(acc[mt][nt][2], acc[mt][nt][3]);
        }
    }
}

// ---------------- combine GEMM1 partials: h1 = relu(sum_z p1 + b1[col])
__global__ void combine1(const float* __restrict__ b1)
{
    const int i4 = blockIdx.x * 256 + threadIdx.x;   // 98304 float4
    float4 r = reinterpret_cast<const float4*>(g_p1)[i4];
#pragma unroll
    for (int zz = 1; zz < KSPLIT; zz++) {
        const float4 p = reinterpret_cast<const float4*>(g_p1 + (size_t)zz * S_BF)[i4];
        r.x += p.x; r.y += p.y; r.z += p.z; r.w += p.w;
    }
    const float4 bb = reinterpret_cast<const float4*>(b1)[i4 & 255];
    r.x = fmaxf(r.x + bb.x, 0.0f);
    r.y = fmaxf(r.y + bb.y, 0.0f);
    r.z = fmaxf(r.z + bb.z, 0.0f);
    r.w = fmaxf(r.w + bb.w, 0.0f);
    reinterpret_cast<float4*>(g_h1)[i4] = r;
}

// ---------------- combine GEMM2 partials + bias + gumbel, argmax + softmax-at-max
__global__ void row_softmax_argmax(const float* __restrict__ b2,
                                   const float* __restrict__ gumbel)
{
    const int r = blockIdx.x;
    const int tid = threadIdx.x;  // 256
    __shared__ float t[F_DIM];
    __shared__ float sv[256];
    __shared__ int   si[256];

    const size_t b4 = (size_t)r * (F_DIM / 4);
    {
        float4 v = reinterpret_cast<const float4*>(g_p2)[b4 + tid];
#pragma unroll
        for (int zz = 1; zz < KSPLIT; zz++) {
            const float4 p = reinterpret_cast<const float4*>(g_p2 + (size_t)zz * S_BF)[b4 + tid];
            v.x += p.x; v.y += p.y; v.z += p.z; v.w += p.w;
        }
        const float4 bb = reinterpret_cast<const float4*>(b2)[tid];
        const float4 gg = reinterpret_cast<const float4*>(gumbel)[b4 + tid];
        v.x += bb.x + gg.x; v.y += bb.y + gg.y; v.z += bb.z + gg.z; v.w += bb.w + gg.w;
        reinterpret_cast<float4*>(t)[tid] = v;
    }
    __syncthreads();

    float bv = -3.402823466e38f;
    int bi = 0;
    for (int f = tid; f < F_DIM; f += 256) {
        float v = t[f];
        if (v > bv) { bv = v; bi = f; }
    }
    sv[tid] = bv; si[tid] = bi;
    __syncthreads();
    for (int s = 128; s > 0; s >>= 1) {
        if (tid < s) {
            float ov = sv[tid + s]; int oi = si[tid + s];
            if (ov > sv[tid] || (ov == sv[tid] && oi < si[tid])) { sv[tid] = ov; si[tid] = oi; }
        }
        __syncthreads();
    }
    const float mx = sv[0];
    const int   ix = si[0];
    __syncthreads();

    float lsum = 0.0f;
    for (int f = tid; f < F_DIM; f += 256) lsum += expf(t[f] - mx);
    sv[tid] = lsum;
    __syncthreads();
    for (int s = 128; s > 0; s >>= 1) {
        if (tid < s) sv[tid] += sv[tid + s];
        __syncthreads();
    }
    if (tid == 0) {
        g_amax[r] = ix;
        float smax = 1.0f / sv[0];
        float h = __fadd_rn(__fadd_rn(1.0f, -smax), smax);
        g_hval[r] = h;
    }
}

// ---------------- invert argmax: per-feature count + deterministic hval list
__global__ void build_lists()
{
    __shared__ int sa[B_ROWS];
    const int tid = threadIdx.x; // 1024
    if (tid < B_ROWS) sa[tid] = g_amax[tid];
    __syncthreads();
    if (tid < F_DIM) {
        int c = 0;
        for (int j = 0; j < B_ROWS; j++) c += (sa[j] == tid) ? 1 : 0;
        g_count[tid] = c;
    }
    if (tid < B_ROWS) {
        int a = sa[tid];
        int slot = 0;
        for (int j = 0; j < tid; j++) slot += (sa[j] == a) ? 1 : 0;
        g_list[(size_t)a * B_ROWS + slot] = g_hval[tid];
    }
}

// ---------------- final: pr[i,f] = aB*(B*q0 + corrections) + beta
__global__ void final_kernel(const float* __restrict__ W3, const float* __restrict__ b3,
                             float* __restrict__ out, float aB, float beta)
{
    const int i = blockIdx.x;
    const int tid = threadIdx.x; // 256
    const float hvi = g_hval[i];
    const int ai = g_amax[i];

    for (int f = tid; f < F_DIM; f += 256) {
        float z = __fmul_rn(hvi, W3[(size_t)f * F_DIM + ai]) + b3[f];
        float q0 = 1.0f / (1.0f + GAMMA_C * z * z);
        float acc = 384.0f * q0;
        int c = g_count[f];
        for (int s = 0; s < c; s++) {
            float d = z - g_list[(size_t)f * B_ROWS + s];
            acc += 1.0f / (1.0f + GAMMA_C * d * d) - q0;
        }
        out[(size_t)i * F_DIM + f] = aB * acc + beta;
    }
}

extern "C" void kernel_launch(void* const* d_in, const int* in_sizes, int n_in,
                              void* d_out, int out_size)
{
    const float* x      = (const float*)d_in[0];
    const float* m      = (const float*)d_in[1];
    const float* gumbel = (const float*)d_in[2];
    const float* W1     = (const float*)d_in[3];
    const float* b1     = (const float*)d_in[4];
    const float* W2     = (const float*)d_in[5];
    const float* b2     = (const float*)d_in[6];
    const float* W3     = (const float*)d_in[7];
    const float* b3     = (const float*)d_in[8];
    float* out = (float*)d_out;

    double s = 0.0;
    for (int k = 1; k <= B_ROWS - 1; k++) s += 1.0 / (double)k;
    double theta = 1.0 / s;
    float alpha = (float)((double)B_ROWS / ((double)B_ROWS + theta));
    float beta  = (float)(0.5 * theta / ((double)B_ROWS + theta));
    float aB    = alpha / (float)B_ROWS;

    // GEMM1: partials of [x|m] @ W1^T   M=384, N=1024, K=2048, split-K=6
    gemm_mma<1><<<dim3(8, 3, KSPLIT), 256>>>(x, m, W1, 2048);
    combine1<<<384, 256>>>(b1);

    // GEMM2: partials of h1 @ W2^T      M=384, N=1024, K=1024, split-K=6
    gemm_mma<2><<<dim3(8, 3, KSPLIT), 256>>>(nullptr, nullptr, W2, 1024);

    row_softmax_argmax<<<B_ROWS, 256>>>(b2, gumbel);
    build_lists<<<1, 1024>>>();
    final_kernel<<<B_ROWS, 256>>>(W3, b3, out, aB, beta);
}